// round 2
// baseline (speedup 1.0000x reference)
#include <cuda_runtime.h>

// Problem dims
#define B_   256
#define T_   512
#define F_   64
#define H_   512
#define OUTC 1536

// Decomposition
#define NGB  4      // batch groups (64 batches each)
#define NHT  32     // hidden tiles (16 hidden units each)
#define NCTA 128
#define NTHR 256
#define KTOT 576    // 512 (h) + 64 (x)
#define CHK  32
#define NCH  18

typedef unsigned long long u64;

// SMEM float offsets
#define WS_OFF   0        // Ws  [576][64] floats             = 36864 f
#define HS_OFF   36864    // hs  [2][32][64] floats           =  4096 f
#define WS2_OFF  40960    // Ws2 [2][32][64] u64 (splatted)   =  8192 f
#define BIAS_OFF 49152    // 64 floats
#define SMEM_FLOATS 49216
#define SMEM_BYTES (SMEM_FLOATS * 4)   // 196864 B

// Persistent device state (allocations are forbidden; __device__ globals are the sanctioned path)
__device__ float g_h[2][H_ * B_];              // [buf][j*256 + b]
__device__ unsigned g_cnt[NGB * 32];           // arrive counters, 128B apart
__device__ volatile unsigned g_gen[NGB * 32];  // generations,     128B apart

// ---------- helpers ----------
__device__ __forceinline__ void fma2(u64& d, u64 a, u64 b) {
    asm("fma.rn.f32x2 %0, %1, %2, %0;" : "+l"(d) : "l"(a), "l"(b));
}
__device__ __forceinline__ float2 u2f(u64 v) {
    float2 r;
    asm("mov.b64 {%0, %1}, %2;" : "=f"(r.x), "=f"(r.y) : "l"(v));
    return r;
}
__device__ __forceinline__ float sigm(float x) {
    return __fdividef(1.0f, 1.0f + __expf(-x));
}

// group barrier across the 32 CTAs of one batch group (sense-reversal)
__device__ __forceinline__ void group_barrier(int gb) {
    __syncthreads();
    if (threadIdx.x == 0) {
        volatile unsigned* genp = &g_gen[gb * 32];
        unsigned g = *genp;
        __threadfence();
        if (atomicAdd(&g_cnt[gb * 32], 1u) == (NHT - 1)) {
            atomicExch(&g_cnt[gb * 32], 0u);
            __threadfence();
            *genp = g + 1u;
        } else {
            while (*genp == g) { }
        }
    }
    __syncthreads();
}

extern "C" __global__ void __launch_bounds__(NTHR, 1)
lstm_persist(const float* __restrict__ x,    const float* __restrict__ W_ih,
             const float* __restrict__ W_hh, const float* __restrict__ b_ih,
             const float* __restrict__ b_hh, const float* __restrict__ W_fc,
             const float* __restrict__ b_fc, float* __restrict__ out)
{
    extern __shared__ float sm[];
    float* Ws  = sm + WS_OFF;               // [576][64]   natural
    float* hsA = sm + HS_OFF;               // [2][32][64] natural (batch-contig)
    u64*   Ws2 = (u64*)(sm + WS2_OFF);      // [2][32][64] splatted {w,w}
    float* bs  = sm + BIAS_OFF;             // [64]

    const int tid = threadIdx.x;
    const int gb  = blockIdx.x >> 5;        // batch group 0..3
    const int ht  = blockIdx.x & 31;        // hidden tile 0..31
    const int tx  = tid & 15;               // batch sub (4 batches)
    const int ty  = tid >> 4;               // hidden unit within tile

    // ---- one-time init: stage W slice into SMEM (576 k x 64 cols, col = jj*4+gate)
    for (int idx = tid; idx < 64 * 144; idx += NTHR) {
        int c = idx / 144, q = idx % 144;
        int g = c & 3, jj = c >> 2;
        int row = g * 512 + ht * 16 + jj;
        int k = q * 4;
        float4 v;
        if (k < 512) v = *(const float4*)(W_hh + (size_t)row * 512 + k);
        else         v = *(const float4*)(W_ih + (size_t)row * 64 + (k - 512));
        Ws[(k + 0) * 64 + c] = v.x;
        Ws[(k + 1) * 64 + c] = v.y;
        Ws[(k + 2) * 64 + c] = v.z;
        Ws[(k + 3) * 64 + c] = v.w;
    }
    if (tid < 64) {
        int g = tid & 3, jj = tid >> 2;
        int row = g * 512 + ht * 16 + jj;
        bs[tid] = b_ih[row] + b_hh[row];
    }
    // zero h0: each CTA zeroes exactly its producer region
    {
        int j = ht * 16 + ty;
        float4 z = make_float4(0.f, 0.f, 0.f, 0.f);
        __stcg((float4*)&g_h[0][j * B_ + gb * 64 + tx * 4], z);
    }
    __threadfence();
    group_barrier(gb);

    const int j   = ht * 16 + ty;           // global hidden unit
    const int bb0 = gb * 64 + tx * 4;       // first of this thread's 4 batches
    const float bI = bs[ty * 4 + 0];
    const float bF = bs[ty * 4 + 1];
    const float bG = bs[ty * 4 + 2];
    const float bO = bs[ty * 4 + 3];

    float cst[4] = {0.f, 0.f, 0.f, 0.f};    // cell state, in registers forever

    for (int t = 0; t < T_; t++) {
        const int cb = t & 1, nb = cb ^ 1;
        const float* hsrc = g_h[cb];

        u64 acc[4][2];
        #pragma unroll
        for (int g = 0; g < 4; g++) { acc[g][0] = 0ull; acc[g][1] = 0ull; }

        // ---- stage chunk 0 (h) + splat W chunk 0
        {
            int kk0 = tid >> 4, bq = (tid & 15) * 4;
            float4 pa = __ldcg((const float4*)(hsrc + (kk0) * B_ + gb * 64 + bq));
            float4 pb = __ldcg((const float4*)(hsrc + (kk0 + 16) * B_ + gb * 64 + bq));
            *(float4*)(hsA + kk0 * 64 + bq) = pa;
            *(float4*)(hsA + (kk0 + 16) * 64 + bq) = pb;
            float2* wdst = (float2*)(Ws2);
            #pragma unroll
            for (int e = 0; e < 8; e++) {
                int i = tid + e * 256;
                float w = Ws[i];
                wdst[i] = make_float2(w, w);
            }
        }
        __syncthreads();

        for (int ch = 0; ch < NCH; ch++) {
            const int cs = ch & 1, ns = cs ^ 1;
            const bool nx  = (ch + 1 < NCH);
            const bool nxh = (ch + 1 < 16);

            // prefetch next chunk into registers (hide L2 latency behind compute)
            float4 pa, pb;
            const int kk0 = tid >> 4, bq = (tid & 15) * 4;
            const int bbx = tid >> 2, fo = (tid & 3) * 8;
            if (nxh) {
                int kc = (ch + 1) * CHK;
                pa = __ldcg((const float4*)(hsrc + (kc + kk0) * B_ + gb * 64 + bq));
                pb = __ldcg((const float4*)(hsrc + (kc + kk0 + 16) * B_ + gb * 64 + bq));
            } else if (nx) {
                int fb = (ch + 1 - 16) * CHK + fo;
                const float* xp = x + ((size_t)(gb * 64 + bbx) * T_ + t) * F_ + fb;
                pa = __ldg((const float4*)xp);
                pb = __ldg((const float4*)(xp + 4));
            }

            // ---- compute 32 k's on buffer cs: 3 LDS.128 + 8 fma.f32x2 per k
            const ulonglong2* hp = (const ulonglong2*)(hsA + cs * 2048);
            const ulonglong2* wp = (const ulonglong2*)(Ws2 + cs * 2048);
            #pragma unroll
            for (int kk = 0; kk < CHK; kk++) {
                ulonglong2 hv  = hp[kk * 16 + tx];          // batches (q0,q1),(q2,q3)
                ulonglong2 w01 = wp[kk * 32 + ty * 2];      // gates i,f splatted
                ulonglong2 w23 = wp[kk * 32 + ty * 2 + 1];  // gates g,o splatted
                fma2(acc[0][0], w01.x, hv.x); fma2(acc[0][1], w01.x, hv.y);
                fma2(acc[1][0], w01.y, hv.x); fma2(acc[1][1], w01.y, hv.y);
                fma2(acc[2][0], w23.x, hv.x); fma2(acc[2][1], w23.x, hv.y);
                fma2(acc[3][0], w23.y, hv.x); fma2(acc[3][1], w23.y, hv.y);
            }

            if (nx) {
                // store prefetched A-chunk
                if (nxh) {
                    *(float4*)(hsA + ns * 2048 + kk0 * 64 + bq) = pa;
                    *(float4*)(hsA + ns * 2048 + (kk0 + 16) * 64 + bq) = pb;
                } else {
                    float* hd = hsA + ns * 2048;
                    hd[(fo + 0) * 64 + bbx] = pa.x;
                    hd[(fo + 1) * 64 + bbx] = pa.y;
                    hd[(fo + 2) * 64 + bbx] = pa.z;
                    hd[(fo + 3) * 64 + bbx] = pa.w;
                    hd[(fo + 4) * 64 + bbx] = pb.x;
                    hd[(fo + 5) * 64 + bbx] = pb.y;
                    hd[(fo + 6) * 64 + bbx] = pb.z;
                    hd[(fo + 7) * 64 + bbx] = pb.w;
                }
                // splat next W chunk (SMEM -> SMEM)
                int kc = (ch + 1) * CHK;
                float2* wdst = (float2*)(Ws2 + ns * 2048);
                #pragma unroll
                for (int e = 0; e < 8; e++) {
                    int i = tid + e * 256;
                    float w = Ws[kc * 64 + i];
                    wdst[i] = make_float2(w, w);
                }
                __syncthreads();
            }
        }

        // ---- gates -> state update (all 4 gates of hidden unit j, 4 batches)
        float2 i01 = u2f(acc[0][0]), i23 = u2f(acc[0][1]);
        float2 f01 = u2f(acc[1][0]), f23 = u2f(acc[1][1]);
        float2 g01 = u2f(acc[2][0]), g23 = u2f(acc[2][1]);
        float2 o01 = u2f(acc[3][0]), o23 = u2f(acc[3][1]);
        float gI[4] = {i01.x, i01.y, i23.x, i23.y};
        float gF[4] = {f01.x, f01.y, f23.x, f23.y};
        float gG[4] = {g01.x, g01.y, g23.x, g23.y};
        float gO[4] = {o01.x, o01.y, o23.x, o23.y};

        float4 hv4;
        float ho[4];
        #pragma unroll
        for (int q = 0; q < 4; q++) {
            float iv = sigm(gI[q] + bI);
            float fv = sigm(gF[q] + bF);
            float gv = tanhf(gG[q] + bG);
            float ov = sigm(gO[q] + bO);
            float cv = fv * cst[q] + iv * gv;
            cst[q] = cv;
            ho[q] = ov * tanhf(cv);
        }
        hv4 = make_float4(ho[0], ho[1], ho[2], ho[3]);
        __stcg((float4*)&g_h[nb][j * B_ + bb0], hv4);
        __threadfence();
        group_barrier(gb);
    }

    // ================= FC head: out[b, r] = h_fin[b,:] . W_fc[r,:] + b_fc[r] ==========
    // h_fin is in g_h[0] (512 steps -> buffer (512)&1 = 0). Reuse Ws SMEM as hss[j][64].
    for (int idx = tid; idx < (H_ * 64) / 4; idx += NTHR) {
        int jj2 = idx >> 4, q = idx & 15;
        *(float4*)(sm + jj2 * 64 + q * 4) =
            __ldcg((const float4*)(g_h[0] + jj2 * B_ + gb * 64 + q * 4));
    }
    __syncthreads();

    const int tx2 = tid & 15;   // 4 batches
    const int ty2 = tid >> 4;   // 3 output cols
    #pragma unroll
    for (int oi = 0; oi < 3; oi++) {
        int r = ht * 48 + ty2 * 3 + oi;
        const float4* wr = (const float4*)(W_fc + (size_t)r * H_);
        float a0, a1, a2, a3;
        a0 = a1 = a2 = a3 = b_fc[r];
        #pragma unroll 4
        for (int j4 = 0; j4 < H_ / 4; j4++) {
            float4 w4 = __ldg(wr + j4);
            float4 h0 = *(const float4*)(sm + (j4 * 4 + 0) * 64 + tx2 * 4);
            float4 h1 = *(const float4*)(sm + (j4 * 4 + 1) * 64 + tx2 * 4);
            float4 h2 = *(const float4*)(sm + (j4 * 4 + 2) * 64 + tx2 * 4);
            float4 h3 = *(const float4*)(sm + (j4 * 4 + 3) * 64 + tx2 * 4);
            a0 += h0.x * w4.x + h1.x * w4.y + h2.x * w4.z + h3.x * w4.w;
            a1 += h0.y * w4.x + h1.y * w4.y + h2.y * w4.z + h3.y * w4.w;
            a2 += h0.z * w4.x + h1.z * w4.y + h2.z * w4.z + h3.z * w4.w;
            a3 += h0.w * w4.x + h1.w * w4.y + h2.w * w4.z + h3.w * w4.w;
        }
        int bbase = gb * 64 + tx2 * 4;
        out[(size_t)(bbase + 0) * OUTC + r] = a0;
        out[(size_t)(bbase + 1) * OUTC + r] = a1;
        out[(size_t)(bbase + 2) * OUTC + r] = a2;
        out[(size_t)(bbase + 3) * OUTC + r] = a3;
    }
}

extern "C" void kernel_launch(void* const* d_in, const int* in_sizes, int n_in,
                              void* d_out, int out_size) {
    const float* x    = (const float*)d_in[0];
    const float* W_ih = (const float*)d_in[1];
    const float* W_hh = (const float*)d_in[2];
    const float* b_ih = (const float*)d_in[3];
    const float* b_hh = (const float*)d_in[4];
    const float* W_fc = (const float*)d_in[5];
    const float* b_fc = (const float*)d_in[6];
    float* out = (float*)d_out;

    cudaFuncSetAttribute(lstm_persist,
                         cudaFuncAttributeMaxDynamicSharedMemorySize, SMEM_BYTES);
    lstm_persist<<<NCTA, NTHR, SMEM_BYTES>>>(x, W_ih, W_hh, b_ih, b_hh, W_fc, b_fc, out);
}

// round 3
// speedup vs baseline: 1.0534x; 1.0534x over previous
#include <cuda_runtime.h>

// Problem dims
#define B_   256
#define T_   512
#define F_   64
#define H_   512
#define OUTC 1536

// Decomposition
#define NGB  4      // batch groups (64 batches each)
#define NHT  32     // hidden tiles (16 hidden units each)
#define NCTA 128
#define NTHR 256
#define KTOT 576    // 512 (h) + 64 (x)
#define CHK  32
#define NCH  18

typedef unsigned long long u64;

// SMEM float offsets
#define WS_OFF   0        // Ws  [576][64] floats             = 36864 f
#define HS_OFF   36864    // hs  [2][32][64] floats           =  4096 f
#define WS2_OFF  40960    // Ws2 [2][32][64] u64 (splatted)   =  8192 f
#define BIAS_OFF 49152    // 64 floats
#define SMEM_FLOATS 49216
#define SMEM_BYTES (SMEM_FLOATS * 4)   // 196864 B

// Persistent device state (allocations are forbidden; __device__ globals are the sanctioned path)
__device__ float g_h[2][H_ * B_];              // [buf][j*256 + b]
__device__ unsigned g_cnt[NGB * 32];           // arrive counters, 128B apart
__device__ volatile unsigned g_gen[NGB * 32];  // generations,     128B apart

// ---------- helpers ----------
__device__ __forceinline__ void fma2(u64& d, u64 a, u64 b) {
    asm("fma.rn.f32x2 %0, %1, %2, %0;" : "+l"(d) : "l"(a), "l"(b));
}
__device__ __forceinline__ float2 u2f(u64 v) {
    float2 r;
    asm("mov.b64 {%0, %1}, %2;" : "=f"(r.x), "=f"(r.y) : "l"(v));
    return r;
}
__device__ __forceinline__ float sigm(float x) {
    return __fdividef(1.0f, 1.0f + __expf(-x));
}

// group barrier across the 32 CTAs of one batch group (sense-reversal)
__device__ __forceinline__ void group_barrier(int gb) {
    __syncthreads();
    if (threadIdx.x == 0) {
        volatile unsigned* genp = &g_gen[gb * 32];
        unsigned g = *genp;
        __threadfence();
        if (atomicAdd(&g_cnt[gb * 32], 1u) == (NHT - 1)) {
            atomicExch(&g_cnt[gb * 32], 0u);
            __threadfence();
            *genp = g + 1u;
        } else {
            while (*genp == g) { }
        }
    }
    __syncthreads();
}

extern "C" __global__ void __launch_bounds__(NTHR, 1)
lstm_persist(const float* __restrict__ x,    const float* __restrict__ W_ih,
             const float* __restrict__ W_hh, const float* __restrict__ b_ih,
             const float* __restrict__ b_hh, const float* __restrict__ W_fc,
             const float* __restrict__ b_fc, float* __restrict__ out)
{
    extern __shared__ float sm[];
    float* Ws  = sm + WS_OFF;               // [576][64]   natural
    float* hsA = sm + HS_OFF;               // [2][32][64] natural (batch-contig)
    u64*   Ws2 = (u64*)(sm + WS2_OFF);      // [2][32][64] splatted {w,w}
    float* bs  = sm + BIAS_OFF;             // [64]

    const int tid = threadIdx.x;
    const int gb  = blockIdx.x >> 5;        // batch group 0..3
    const int ht  = blockIdx.x & 31;        // hidden tile 0..31
    const int tx  = tid & 15;               // batch sub (4 batches)
    const int ty  = tid >> 4;               // hidden unit within tile

    // ---- one-time init: stage W slice into SMEM (576 k x 64 cols, col = jj*4+gate)
    for (int idx = tid; idx < 64 * 144; idx += NTHR) {
        int c = idx / 144, q = idx % 144;
        int g = c & 3, jj = c >> 2;
        int row = g * 512 + ht * 16 + jj;
        int k = q * 4;
        float4 v;
        if (k < 512) v = *(const float4*)(W_hh + (size_t)row * 512 + k);
        else         v = *(const float4*)(W_ih + (size_t)row * 64 + (k - 512));
        Ws[(k + 0) * 64 + c] = v.x;
        Ws[(k + 1) * 64 + c] = v.y;
        Ws[(k + 2) * 64 + c] = v.z;
        Ws[(k + 3) * 64 + c] = v.w;
    }
    if (tid < 64) {
        int g = tid & 3, jj = tid >> 2;
        int row = g * 512 + ht * 16 + jj;
        bs[tid] = b_ih[row] + b_hh[row];
    }
    // zero h0: each CTA zeroes exactly its producer region
    {
        int j = ht * 16 + ty;
        float4 z = make_float4(0.f, 0.f, 0.f, 0.f);
        __stcg((float4*)&g_h[0][j * B_ + gb * 64 + tx * 4], z);
    }
    __threadfence();
    group_barrier(gb);

    const int j   = ht * 16 + ty;           // global hidden unit
    const int bb0 = gb * 64 + tx * 4;       // first of this thread's 4 batches
    const float bI = bs[ty * 4 + 0];
    const float bF = bs[ty * 4 + 1];
    const float bG = bs[ty * 4 + 2];
    const float bO = bs[ty * 4 + 3];

    float cst[4] = {0.f, 0.f, 0.f, 0.f};    // cell state, in registers forever

    for (int t = 0; t < T_; t++) {
        const int cb = t & 1, nb = cb ^ 1;
        const float* hsrc = g_h[cb];

        u64 acc[4][2];
        #pragma unroll
        for (int g = 0; g < 4; g++) { acc[g][0] = 0ull; acc[g][1] = 0ull; }

        // ---- stage chunk 0 (h) + splat W chunk 0
        {
            int kk0 = tid >> 4, bq = (tid & 15) * 4;
            float4 pa = __ldcg((const float4*)(hsrc + (kk0) * B_ + gb * 64 + bq));
            float4 pb = __ldcg((const float4*)(hsrc + (kk0 + 16) * B_ + gb * 64 + bq));
            *(float4*)(hsA + kk0 * 64 + bq) = pa;
            *(float4*)(hsA + (kk0 + 16) * 64 + bq) = pb;
            float2* wdst = (float2*)(Ws2);
            #pragma unroll
            for (int e = 0; e < 8; e++) {
                int i = tid + e * 256;
                float w = Ws[i];
                wdst[i] = make_float2(w, w);
            }
        }
        __syncthreads();

        for (int ch = 0; ch < NCH; ch++) {
            const int cs = ch & 1, ns = cs ^ 1;
            const bool nx  = (ch + 1 < NCH);
            const bool nxh = (ch + 1 < 16);

            // prefetch next chunk into registers (hide L2 latency behind compute)
            float4 pa, pb;
            const int kk0 = tid >> 4, bq = (tid & 15) * 4;
            const int bbx = tid >> 2, fo = (tid & 3) * 8;
            if (nxh) {
                int kc = (ch + 1) * CHK;
                pa = __ldcg((const float4*)(hsrc + (kc + kk0) * B_ + gb * 64 + bq));
                pb = __ldcg((const float4*)(hsrc + (kc + kk0 + 16) * B_ + gb * 64 + bq));
            } else if (nx) {
                int fb = (ch + 1 - 16) * CHK + fo;
                const float* xp = x + ((size_t)(gb * 64 + bbx) * T_ + t) * F_ + fb;
                pa = __ldg((const float4*)xp);
                pb = __ldg((const float4*)(xp + 4));
            }

            // ---- compute 32 k's on buffer cs: 3 LDS.128 + 8 fma.f32x2 per k
            const ulonglong2* hp = (const ulonglong2*)(hsA + cs * 2048);
            const ulonglong2* wp = (const ulonglong2*)(Ws2 + cs * 2048);
            #pragma unroll
            for (int kk = 0; kk < CHK; kk++) {
                ulonglong2 hv  = hp[kk * 16 + tx];          // batches (q0,q1),(q2,q3)
                ulonglong2 w01 = wp[kk * 32 + ty * 2];      // gates i,f splatted
                ulonglong2 w23 = wp[kk * 32 + ty * 2 + 1];  // gates g,o splatted
                fma2(acc[0][0], w01.x, hv.x); fma2(acc[0][1], w01.x, hv.y);
                fma2(acc[1][0], w01.y, hv.x); fma2(acc[1][1], w01.y, hv.y);
                fma2(acc[2][0], w23.x, hv.x); fma2(acc[2][1], w23.x, hv.y);
                fma2(acc[3][0], w23.y, hv.x); fma2(acc[3][1], w23.y, hv.y);
            }

            if (nx) {
                // store prefetched A-chunk
                if (nxh) {
                    *(float4*)(hsA + ns * 2048 + kk0 * 64 + bq) = pa;
                    *(float4*)(hsA + ns * 2048 + (kk0 + 16) * 64 + bq) = pb;
                } else {
                    float* hd = hsA + ns * 2048;
                    hd[(fo + 0) * 64 + bbx] = pa.x;
                    hd[(fo + 1) * 64 + bbx] = pa.y;
                    hd[(fo + 2) * 64 + bbx] = pa.z;
                    hd[(fo + 3) * 64 + bbx] = pa.w;
                    hd[(fo + 4) * 64 + bbx] = pb.x;
                    hd[(fo + 5) * 64 + bbx] = pb.y;
                    hd[(fo + 6) * 64 + bbx] = pb.z;
                    hd[(fo + 7) * 64 + bbx] = pb.w;
                }
                // splat next W chunk (SMEM -> SMEM)
                int kc = (ch + 1) * CHK;
                float2* wdst = (float2*)(Ws2 + ns * 2048);
                #pragma unroll
                for (int e = 0; e < 8; e++) {
                    int i = tid + e * 256;
                    float w = Ws[kc * 64 + i];
                    wdst[i] = make_float2(w, w);
                }
                __syncthreads();
            }
        }

        // ---- gates -> state update (all 4 gates of hidden unit j, 4 batches)
        float2 i01 = u2f(acc[0][0]), i23 = u2f(acc[0][1]);
        float2 f01 = u2f(acc[1][0]), f23 = u2f(acc[1][1]);
        float2 g01 = u2f(acc[2][0]), g23 = u2f(acc[2][1]);
        float2 o01 = u2f(acc[3][0]), o23 = u2f(acc[3][1]);
        float gI[4] = {i01.x, i01.y, i23.x, i23.y};
        float gF[4] = {f01.x, f01.y, f23.x, f23.y};
        float gG[4] = {g01.x, g01.y, g23.x, g23.y};
        float gO[4] = {o01.x, o01.y, o23.x, o23.y};

        float4 hv4;
        float ho[4];
        #pragma unroll
        for (int q = 0; q < 4; q++) {
            float iv = sigm(gI[q] + bI);
            float fv = sigm(gF[q] + bF);
            float gv = tanhf(gG[q] + bG);
            float ov = sigm(gO[q] + bO);
            float cv = fv * cst[q] + iv * gv;
            cst[q] = cv;
            ho[q] = ov * tanhf(cv);
        }
        hv4 = make_float4(ho[0], ho[1], ho[2], ho[3]);
        __stcg((float4*)&g_h[nb][j * B_ + bb0], hv4);
        __threadfence();
        group_barrier(gb);
    }

    // ================= FC head: out[b, r] = h_fin[b,:] . W_fc[r,:] + b_fc[r] ==========
    // h_fin is in g_h[0] (512 steps -> buffer (512)&1 = 0). Reuse Ws SMEM as hss[j][64].
    for (int idx = tid; idx < (H_ * 64) / 4; idx += NTHR) {
        int jj2 = idx >> 4, q = idx & 15;
        *(float4*)(sm + jj2 * 64 + q * 4) =
            __ldcg((const float4*)(g_h[0] + jj2 * B_ + gb * 64 + q * 4));
    }
    __syncthreads();

    const int tx2 = tid & 15;   // 4 batches
    const int ty2 = tid >> 4;   // 3 output cols
    #pragma unroll
    for (int oi = 0; oi < 3; oi++) {
        int r = ht * 48 + ty2 * 3 + oi;
        const float4* wr = (const float4*)(W_fc + (size_t)r * H_);
        float a0, a1, a2, a3;
        a0 = a1 = a2 = a3 = b_fc[r];
        #pragma unroll 4
        for (int j4 = 0; j4 < H_ / 4; j4++) {
            float4 w4 = __ldg(wr + j4);
            float4 h0 = *(const float4*)(sm + (j4 * 4 + 0) * 64 + tx2 * 4);
            float4 h1 = *(const float4*)(sm + (j4 * 4 + 1) * 64 + tx2 * 4);
            float4 h2 = *(const float4*)(sm + (j4 * 4 + 2) * 64 + tx2 * 4);
            float4 h3 = *(const float4*)(sm + (j4 * 4 + 3) * 64 + tx2 * 4);
            a0 += h0.x * w4.x + h1.x * w4.y + h2.x * w4.z + h3.x * w4.w;
            a1 += h0.y * w4.x + h1.y * w4.y + h2.y * w4.z + h3.y * w4.w;
            a2 += h0.z * w4.x + h1.z * w4.y + h2.z * w4.z + h3.z * w4.w;
            a3 += h0.w * w4.x + h1.w * w4.y + h2.w * w4.z + h3.w * w4.w;
        }
        int bbase = gb * 64 + tx2 * 4;
        out[(size_t)(bbase + 0) * OUTC + r] = a0;
        out[(size_t)(bbase + 1) * OUTC + r] = a1;
        out[(size_t)(bbase + 2) * OUTC + r] = a2;
        out[(size_t)(bbase + 3) * OUTC + r] = a3;
    }
}

extern "C" void kernel_launch(void* const* d_in, const int* in_sizes, int n_in,
                              void* d_out, int out_size) {
    const float* x    = (const float*)d_in[0];
    const float* W_ih = (const float*)d_in[1];
    const float* W_hh = (const float*)d_in[2];
    const float* b_ih = (const float*)d_in[3];
    const float* b_hh = (const float*)d_in[4];
    const float* W_fc = (const float*)d_in[5];
    const float* b_fc = (const float*)d_in[6];
    float* out = (float*)d_out;

    cudaFuncSetAttribute(lstm_persist,
                         cudaFuncAttributeMaxDynamicSharedMemorySize, SMEM_BYTES);
    lstm_persist<<<NCTA, NTHR, SMEM_BYTES>>>(x, W_ih, W_hh, b_ih, b_hh, W_fc, b_fc, out);
}

// round 5
// speedup vs baseline: 2.7075x; 2.5703x over previous
#include <cuda_runtime.h>
#include <cuda_bf16.h>
#include <cstdint>

#define B_   256
#define T_   512
#define H_   512
#define OUTC 1536

#define NCTA 128
#define NTHR 256

#define WSTRIDE 1168            // 576*2 + 16 pad -> ldmatrix conflict-free
#define OFF_WHI  0
#define OFF_WLO  74752          // 64*1168
#define OFF_A0   149504         // A chunk: [hi 8192 | lo 8192]
#define OFF_A1   165888
#define OFF_BIAS 182272
#define SMEM_BYTES 182528

// ---------------- persistent device scratch ----------------
__device__ unsigned short g_hb[2][2][B_ * H_];             // [parity][hi/lo][b*512+j]
__device__ unsigned short g_x2[2][(size_t)B_ * T_ * 64];   // [hi/lo][b][t][f]
__device__ float g_hf[H_ * B_];                            // final h, [j*256+b]
__device__ unsigned g_cnt[4 * 32];
__device__ volatile unsigned g_gen[4 * 32];

// ---------------- helpers ----------------
__device__ __forceinline__ uint32_t smem_u32(const void* p) {
    uint32_t a;
    asm("{ .reg .u64 t; cvta.to.shared.u64 t, %1; cvt.u32.u64 %0, t; }" : "=r"(a) : "l"(p));
    return a;
}
__device__ __forceinline__ void split1(float v, unsigned short& hi, unsigned short& lo) {
    __nv_bfloat16 h = __float2bfloat16_rn(v);
    float rem = v - __bfloat162float(h);
    hi = __bfloat16_as_ushort(h);
    lo = __bfloat16_as_ushort(__float2bfloat16_rn(rem));
}
__device__ __forceinline__ float sigm(float x) {
    return __fdividef(1.0f, 1.0f + __expf(-x));
}
__device__ __forceinline__ float tanh_(float x) {
    float e = __expf(2.0f * x);
    return 1.0f - __fdividef(2.0f, e + 1.0f);
}
__device__ __forceinline__ void cpa(uint32_t dst, const void* src) {
    asm volatile("cp.async.cg.shared.global [%0], [%1], 16;" :: "r"(dst), "l"(src) : "memory");
}
__device__ __forceinline__ void cpa_commit() { asm volatile("cp.async.commit_group;" ::: "memory"); }
__device__ __forceinline__ void cpa_wait()   { asm volatile("cp.async.wait_group 0;" ::: "memory"); }

__device__ __forceinline__ void ldsm4(uint32_t* r, uint32_t a) {
    asm volatile("ldmatrix.sync.aligned.m8n8.x4.shared.b16 {%0,%1,%2,%3}, [%4];"
                 : "=r"(r[0]), "=r"(r[1]), "=r"(r[2]), "=r"(r[3]) : "r"(a));
}
__device__ __forceinline__ void mma16816(float* c, const uint32_t* a, uint32_t b0, uint32_t b1) {
    asm volatile(
        "mma.sync.aligned.m16n8k16.row.col.f32.bf16.bf16.f32 "
        "{%0,%1,%2,%3}, {%4,%5,%6,%7}, {%8,%9}, {%0,%1,%2,%3};"
        : "+f"(c[0]), "+f"(c[1]), "+f"(c[2]), "+f"(c[3])
        : "r"(a[0]), "r"(a[1]), "r"(a[2]), "r"(a[3]), "r"(b0), "r"(b1));
}

// group barrier across the 32 CTAs of one batch group
__device__ __forceinline__ void gbar(int gb) {
    __threadfence();
    __syncthreads();
    if (threadIdx.x == 0) {
        volatile unsigned* gp = &g_gen[gb * 32];
        unsigned g = *gp;
        if (atomicAdd(&g_cnt[gb * 32], 1u) == 31u) {
            atomicExch(&g_cnt[gb * 32], 0u);
            __threadfence();
            *gp = g + 1u;
        } else {
            while (*gp == g) { }
        }
        __threadfence();
    }
    __syncthreads();
}

// ============ x prep: fp32 -> split bf16 (same [b][t][f] layout) ============
extern "C" __global__ void xsplit(const float* __restrict__ x) {
    size_t i = ((size_t)blockIdx.x * 256 + threadIdx.x) * 4;
    float4 v = __ldg((const float4*)(x + i));
    unsigned short h0, l0, h1, l1, h2, l2, h3, l3;
    split1(v.x, h0, l0); split1(v.y, h1, l1);
    split1(v.z, h2, l2); split1(v.w, h3, l3);
    ushort4 H = {h0, h1, h2, h3}, L = {l0, l1, l2, l3};
    *(ushort4*)(&g_x2[0][i]) = H;
    *(ushort4*)(&g_x2[1][i]) = L;
}

// ============ main persistent kernel ============
extern "C" __global__ void __launch_bounds__(NTHR, 1)
lstm_mma(const float* __restrict__ x,    const float* __restrict__ W_ih,
         const float* __restrict__ W_hh, const float* __restrict__ b_ih,
         const float* __restrict__ b_hh, const float* __restrict__ W_fc,
         const float* __restrict__ b_fc, float* __restrict__ out)
{
    extern __shared__ unsigned char smc[];
    const uint32_t sa = smem_u32(smc);
    const int tid = threadIdx.x, lane = tid & 31, w = tid >> 5;
    const int gb = blockIdx.x >> 5, ht = blockIdx.x & 31;
    const int wm = w & 1, wn = w >> 1;
    float* bs = (float*)(smc + OFF_BIAS);

    // ---- W split -> SMEM: row n (= jj*4+gate), k-major, stride 1168B
    for (int idx = tid; idx < 64 * 576; idx += NTHR) {
        int k = idx >> 6, n = idx & 63;
        int row = (n & 3) * 512 + ht * 16 + (n >> 2);
        float v = (k < 512) ? W_hh[(size_t)row * 512 + k] : W_ih[(size_t)row * 64 + (k - 512)];
        unsigned short hi, lo;
        split1(v, hi, lo);
        *(unsigned short*)(smc + OFF_WHI + n * WSTRIDE + k * 2) = hi;
        *(unsigned short*)(smc + OFF_WLO + n * WSTRIDE + k * 2) = lo;
    }
    if (tid < 64) {
        int row = (tid & 3) * 512 + ht * 16 + (tid >> 2);
        bs[tid] = b_ih[row] + b_hh[row];
    }
    // zero h parity-0 for this CTA's (b,j) block
    if (tid < 128) {
        int r = tid >> 1, hh = tid & 1;
        uint4 z = make_uint4(0, 0, 0, 0);
        *(uint4*)(&g_hb[0][0][(size_t)(gb * 64 + r) * 512 + ht * 16 + hh * 8]) = z;
        *(uint4*)(&g_hb[0][1][(size_t)(gb * 64 + r) * 512 + ht * 16 + hh * 8]) = z;
    }
    gbar(gb);

    // per-lane address components
    const int rowl = lane & 15;
    const uint32_t xm = (uint32_t)(lane & 7) << 4;       // A swizzle mask
    const uint32_t kl = (uint32_t)(lane >> 4) * 16;      // A k-half (bytes)
    const int nloc = wn * 16 + (lane & 7) + ((lane >> 4) << 3);
    const uint32_t krel = (uint32_t)((lane >> 3) & 1) * 16;  // B k-half (bytes)
    const uint32_t bBaseHi = sa + OFF_WHI + (uint32_t)nloc * WSTRIDE + krel;
    const uint32_t bBaseLo = sa + OFF_WLO + (uint32_t)nloc * WSTRIDE + krel;
    const uint32_t aRow0 = (uint32_t)(wm * 32 + rowl) * 128;

    const int sr = tid >> 2;            // staging row 0..63
    const int su = (tid & 3) * 2;       // staging 16B units

    float cst[4] = {0.f, 0.f, 0.f, 0.f};
    const int q = lane & 3, mth = q & 1;

    for (int t = 0; t < T_; t++) {
        const int par = t & 1, nb = par ^ 1;

        float acc[2][2][4];
        #pragma unroll
        for (int a1 = 0; a1 < 2; a1++)
            #pragma unroll
            for (int a2 = 0; a2 < 2; a2++)
                #pragma unroll
                for (int a3 = 0; a3 < 4; a3++) acc[a1][a2][a3] = 0.f;

        // stage chunk 0
        #pragma unroll
        for (int s2 = 0; s2 < 2; s2++) {
            int u = su + s2;
            uint32_t doff = (uint32_t)sr * 128 + (((uint32_t)u * 16) ^ ((uint32_t)(sr & 7) << 4));
            size_t o = (size_t)(gb * 64 + sr) * 512 + u * 8;
            cpa(sa + OFF_A0 + doff, &g_hb[par][0][o]);
            cpa(sa + OFF_A0 + 8192 + doff, &g_hb[par][1][o]);
        }
        cpa_commit();
        cpa_wait();
        __syncthreads();

        for (int ch = 0; ch < 9; ch++) {
            const int buf = ch & 1;
            if (ch < 8) {   // prefetch next chunk into other buffer
                int nc = ch + 1;
                uint32_t d0 = sa + ((nc & 1) ? OFF_A1 : OFF_A0);
                #pragma unroll
                for (int s2 = 0; s2 < 2; s2++) {
                    int u = su + s2;
                    uint32_t doff = (uint32_t)sr * 128 + (((uint32_t)u * 16) ^ ((uint32_t)(sr & 7) << 4));
                    const unsigned short *shi, *slo;
                    if (nc < 8) {
                        size_t o = (size_t)(gb * 64 + sr) * 512 + nc * 64 + u * 8;
                        shi = &g_hb[par][0][o]; slo = &g_hb[par][1][o];
                    } else {
                        size_t o = ((size_t)(gb * 64 + sr) * 512 + t) * 64 + u * 8;
                        shi = &g_x2[0][o]; slo = &g_x2[1][o];
                    }
                    cpa(d0 + doff, shi);
                    cpa(d0 + 8192 + doff, slo);
                }
                cpa_commit();
            }

            const uint32_t aB = sa + (buf ? OFF_A1 : OFF_A0);
            const uint32_t bK = (uint32_t)ch * 128;
            #pragma unroll
            for (int kt = 0; kt < 4; kt++) {
                uint32_t kq = (((uint32_t)kt * 32) + kl) ^ xm;
                uint32_t h0[4], h1[4], l0[4], l1[4], bh[4], bl[4];
                ldsm4(h0, aB + aRow0 + kq);
                ldsm4(h1, aB + aRow0 + 2048 + kq);
                ldsm4(l0, aB + 8192 + aRow0 + kq);
                ldsm4(l1, aB + 8192 + aRow0 + 2048 + kq);
                ldsm4(bh, bBaseHi + bK + kt * 32);
                ldsm4(bl, bBaseLo + bK + kt * 32);

                mma16816(acc[0][0], h0, bh[0], bh[1]);
                mma16816(acc[0][1], h0, bh[2], bh[3]);
                mma16816(acc[1][0], h1, bh[0], bh[1]);
                mma16816(acc[1][1], h1, bh[2], bh[3]);
                mma16816(acc[0][0], h0, bl[0], bl[1]);
                mma16816(acc[0][1], h0, bl[2], bl[3]);
                mma16816(acc[1][0], h1, bl[0], bl[1]);
                mma16816(acc[1][1], h1, bl[2], bl[3]);
                mma16816(acc[0][0], l0, bh[0], bh[1]);
                mma16816(acc[0][1], l0, bh[2], bh[3]);
                mma16816(acc[1][0], l1, bh[0], bh[1]);
                mma16816(acc[1][1], l1, bh[2], bh[3]);
            }
            if (ch < 8) { cpa_wait(); __syncthreads(); }
        }

        // ---- epilogue: pair-exchange to assemble all 4 gates per (row, jj)
        float recv[2][4];
        #pragma unroll
        for (int nt = 0; nt < 2; nt++)
            #pragma unroll
            for (int k2 = 0; k2 < 4; k2++) {
                float sv = mth ? acc[0][nt][k2] : acc[1][nt][k2];
                recv[nt][k2] = __shfl_xor_sync(0xffffffffu, sv, 1);
            }
        #pragma unroll
        for (int nt = 0; nt < 2; nt++) {
            int jj = wn * 4 + nt * 2 + (q >> 1);
            float bI = bs[jj * 4 + 0], bF = bs[jj * 4 + 1];
            float bG = bs[jj * 4 + 2], bO = bs[jj * 4 + 3];
            #pragma unroll
            for (int rh = 0; rh < 2; rh++) {
                float o0 = acc[mth][nt][rh * 2 + 0], o1 = acc[mth][nt][rh * 2 + 1];
                float r0 = recv[nt][rh * 2 + 0],     r1 = recv[nt][rh * 2 + 1];
                float I = (mth == 0 ? o0 : r0) + bI;
                float F = (mth == 0 ? o1 : r1) + bF;
                float G = (mth == 0 ? r0 : o0) + bG;
                float O = (mth == 0 ? r1 : o1) + bO;
                float iv = sigm(I), fv = sigm(F), gv = tanh_(G), ov = sigm(O);
                int ci = nt * 2 + rh;
                float cv = fv * cst[ci] + iv * gv;
                cst[ci] = cv;
                float ho = ov * tanh_(cv);
                int row = wm * 32 + mth * 16 + (lane >> 2) + rh * 8;
                int b = gb * 64 + row, j = ht * 16 + jj;
                unsigned short hi, lo;
                split1(ho, hi, lo);
                size_t o = (size_t)b * 512 + j;
                g_hb[nb][0][o] = hi;
                g_hb[nb][1][o] = lo;
                if (t == T_ - 1) g_hf[(size_t)j * 256 + b] = ho;
            }
        }
        gbar(gb);
    }

    // ================= FC head (proven R2 code) =================
    float* smf = (float*)smc;
    for (int idx = tid; idx < (H_ * 64) / 4; idx += NTHR) {
        int jj2 = idx >> 4, qv = idx & 15;
        *(float4*)(smf + jj2 * 64 + qv * 4) =
            __ldcg((const float4*)(g_hf + (size_t)jj2 * 256 + gb * 64 + qv * 4));
    }
    __syncthreads();

    const int tx2 = tid & 15, ty2 = tid >> 4;
    #pragma unroll
    for (int oi = 0; oi < 3; oi++) {
        int r = ht * 48 + ty2 * 3 + oi;
        const float4* wr = (const float4*)(W_fc + (size_t)r * H_);
        float a0, a1, a2, a3;
        a0 = a1 = a2 = a3 = b_fc[r];
        #pragma unroll 4
        for (int j4 = 0; j4 < H_ / 4; j4++) {
            float4 w4 = __ldg(wr + j4);
            float4 h0 = *(const float4*)(smf + (j4 * 4 + 0) * 64 + tx2 * 4);
            float4 h1 = *(const float4*)(smf + (j4 * 4 + 1) * 64 + tx2 * 4);
            float4 h2 = *(const float4*)(smf + (j4 * 4 + 2) * 64 + tx2 * 4);
            float4 h3 = *(const float4*)(smf + (j4 * 4 + 3) * 64 + tx2 * 4);
            a0 += h0.x * w4.x + h1.x * w4.y + h2.x * w4.z + h3.x * w4.w;
            a1 += h0.y * w4.x + h1.y * w4.y + h2.y * w4.z + h3.y * w4.w;
            a2 += h0.z * w4.x + h1.z * w4.y + h2.z * w4.z + h3.z * w4.w;
            a3 += h0.w * w4.x + h1.w * w4.y + h2.w * w4.z + h3.w * w4.w;
        }
        int bbase = gb * 64 + tx2 * 4;
        out[(size_t)(bbase + 0) * OUTC + r] = a0;
        out[(size_t)(bbase + 1) * OUTC + r] = a1;
        out[(size_t)(bbase + 2) * OUTC + r] = a2;
        out[(size_t)(bbase + 3) * OUTC + r] = a3;
    }
}

extern "C" void kernel_launch(void* const* d_in, const int* in_sizes, int n_in,
                              void* d_out, int out_size) {
    const float* x    = (const float*)d_in[0];
    const float* W_ih = (const float*)d_in[1];
    const float* W_hh = (const float*)d_in[2];
    const float* b_ih = (const float*)d_in[3];
    const float* b_hh = (const float*)d_in[4];
    const float* W_fc = (const float*)d_in[5];
    const float* b_fc = (const float*)d_in[6];
    float* out = (float*)d_out;

    xsplit<<<8192, 256>>>(x);
    cudaFuncSetAttribute(lstm_mma, cudaFuncAttributeMaxDynamicSharedMemorySize, SMEM_BYTES);
    lstm_mma<<<NCTA, NTHR, SMEM_BYTES>>>(x, W_ih, W_hh, b_ih, b_hh, W_fc, b_fc, out);
}